// round 1
// baseline (speedup 1.0000x reference)
#include <cuda_runtime.h>

#define NC   4096
#define ND   2048
#define NTOT 6144
#define HIDDEN 512
#define NHEAD 8
#define HD   64

// ---------------- scratch (device globals: no allocations allowed) ----------
__device__ float g_x  [NTOT*HIDDEN];
__device__ float g_q  [NTOT*HIDDEN];
__device__ float g_k  [NTOT*HIDDEN];
__device__ float g_v  [NTOT*HIDDEN];
__device__ float g_att[NTOT*HIDDEN];
__device__ float g_h  [NTOT*HIDDEN];
__device__ unsigned g_adj [NC*(ND/32)];   // bit j of word: cd[i][w*32+j]
__device__ unsigned g_adjT[ND*(NC/32)];   // transposed bitmask for d-side queries
__device__ float g_ps[48*HIDDEN];
__device__ float g_pq[48*HIDDEN];
__device__ float g_scale[HIDDEN];
__device__ float g_shift[HIDDEN];

// ---------------- build x = concat(c, d) ------------------------------------
__global__ void copy_x_kernel(const float4* __restrict__ c, const float4* __restrict__ d) {
    int i = blockIdx.x * blockDim.x + threadIdx.x;   // over NTOT*HIDDEN/4
    const int nc4 = NC * HIDDEN / 4;
    float4* x4 = (float4*)g_x;
    if (i < nc4) x4[i] = c[i];
    else         x4[i] = d[i - nc4];
}

// ---------------- pack adjacency into bitmasks -------------------------------
__global__ void pack_adj_kernel(const int* __restrict__ cd) {
    int t = blockIdx.x * blockDim.x + threadIdx.x;   // over NC*(ND/32)
    if (t >= NC * (ND/32)) return;
    int i = t >> 6, w = t & 63;
    const int* p = cd + (size_t)i * ND + w * 32;
    unsigned bits = 0;
    #pragma unroll
    for (int b = 0; b < 32; b++) bits |= (p[b] != 0) ? (1u << b) : 0u;
    g_adj[t] = bits;
}

__global__ void pack_adjT_kernel(const int* __restrict__ cd) {
    int t = blockIdx.x * blockDim.x + threadIdx.x;   // over ND*(NC/32)
    if (t >= ND * (NC/32)) return;
    int w = t >> 11;          // which 32-block of c-side indices (0..127)
    int j = t & 2047;         // d-side index (coalesced across threads)
    unsigned bits = 0;
    #pragma unroll
    for (int b = 0; b < 32; b++)
        bits |= (cd[(size_t)(w * 32 + b) * ND + j] != 0) ? (1u << b) : 0u;
    g_adjT[(size_t)j * (NC/32) + w] = bits;
}

// ---------------- fp32 tiled GEMM: C = A @ W + bias --------------------------
// A rows come from g_x (k<512) or g_att (k>=512, for the concat GEMM).
// outSel: 0->g_q 1->g_k 2->g_v 3->g_h.  M=6144, N=512 fixed, K=Ktot.
__global__ void __launch_bounds__(256)
gemm_kernel(const float* __restrict__ W, const float* __restrict__ bias,
            int outSel, int Ktot)
{
    __shared__ float As[16][128];
    __shared__ float Bs[16][64];
    float* C = (outSel == 0) ? g_q : (outSel == 1) ? g_k : (outSel == 2) ? g_v : g_h;

    int tid = threadIdx.x;
    int tx = tid & 15, ty = tid >> 4;
    int rowBase = blockIdx.y * 128;
    int colBase = blockIdx.x * 64;

    float acc[8][4];
    #pragma unroll
    for (int i = 0; i < 8; i++)
        #pragma unroll
        for (int j = 0; j < 4; j++) acc[i][j] = 0.f;

    for (int k0 = 0; k0 < Ktot; k0 += 16) {
        // load A tile 128x16 (512 float4s)
        #pragma unroll
        for (int l = 0; l < 2; l++) {
            int f = tid + l * 256;
            int r = f >> 2, c4 = f & 3;
            int kk = k0 + c4 * 4;
            const float* src = (kk < HIDDEN)
                ? (g_x   + (size_t)(rowBase + r) * HIDDEN + kk)
                : (g_att + (size_t)(rowBase + r) * HIDDEN + (kk - HIDDEN));
            float4 val = *(const float4*)src;
            As[c4*4+0][r] = val.x; As[c4*4+1][r] = val.y;
            As[c4*4+2][r] = val.z; As[c4*4+3][r] = val.w;
        }
        // load B tile 16x64 (256 float4s)
        {
            int r = tid >> 4, c4 = tid & 15;
            float4 val = *(const float4*)(W + (size_t)(k0 + r) * HIDDEN + colBase + c4 * 4);
            *(float4*)&Bs[r][c4*4] = val;
        }
        __syncthreads();
        #pragma unroll
        for (int kk = 0; kk < 16; kk++) {
            float a[8], b[4];
            #pragma unroll
            for (int i = 0; i < 8; i++) a[i] = As[kk][ty*8 + i];
            #pragma unroll
            for (int j = 0; j < 4; j++) b[j] = Bs[kk][tx*4 + j];
            #pragma unroll
            for (int i = 0; i < 8; i++)
                #pragma unroll
                for (int j = 0; j < 4; j++) acc[i][j] += a[i] * b[j];
        }
        __syncthreads();
    }
    #pragma unroll
    for (int i = 0; i < 8; i++) {
        int row = rowBase + ty*8 + i;
        #pragma unroll
        for (int j = 0; j < 4; j++) {
            int col = colBase + tx*4 + j;
            C[(size_t)row * HIDDEN + col] = acc[i][j] + bias[col];
        }
    }
}

// ---------------- flash attention with bitmask skip --------------------------
// grid: (48 query tiles of 128, 8 heads). 1 thread = 1 query row.
// c-side queries (tiles 0..31) attend only d-side keys; vice versa.
__global__ void __launch_bounds__(128, 2)
attn_kernel()
{
    __shared__ float Ks[64][64];
    __shared__ float Vs[64][64];
    int head = blockIdx.y;
    int tid  = threadIdx.x;
    int qt   = blockIdx.x;
    bool cside = (qt < 32);
    int qrow  = cside ? qt * 128 + tid : NC + (qt - 32) * 128 + tid;
    int kbase = cside ? NC : 0;
    int nkeys = cside ? ND : NC;
    const unsigned* mrow = cside ? (g_adj  + (size_t)qrow * (ND/32))
                                 : (g_adjT + (size_t)(qrow - NC) * (NC/32));

    float Q[64], O[64];
    {
        const float4* qp = (const float4*)(g_q + (size_t)qrow * HIDDEN + head * HD);
        #pragma unroll
        for (int i = 0; i < 16; i++) {
            float4 t = qp[i];
            Q[4*i] = t.x; Q[4*i+1] = t.y; Q[4*i+2] = t.z; Q[4*i+3] = t.w;
        }
    }
    #pragma unroll
    for (int i = 0; i < 64; i++) O[i] = 0.f;
    float m = -1e30f, l = 0.f;

    #pragma unroll 1
    for (int kb = 0; kb < nkeys; kb += 64) {
        #pragma unroll
        for (int i = 0; i < 8; i++) {
            int f = tid + 128 * i;
            int r = f >> 4, c4 = f & 15;
            const float4* ks = (const float4*)(g_k + (size_t)(kbase + kb + r) * HIDDEN + head * HD);
            const float4* vs = (const float4*)(g_v + (size_t)(kbase + kb + r) * HIDDEN + head * HD);
            ((float4*)&Ks[r][0])[c4] = ks[c4];
            ((float4*)&Vs[r][0])[c4] = vs[c4];
        }
        unsigned w0 = mrow[kb >> 5];
        unsigned w1 = mrow[(kb >> 5) + 1];
        __syncthreads();

        #pragma unroll 1
        for (int cc = 0; cc < 64; cc++) {
            unsigned bit = ((cc < 32 ? (w0 >> cc) : (w1 >> (cc - 32))) & 1u);
            if (bit) {
                const float4* kr = (const float4*)&Ks[cc][0];
                float s0 = 0.f, s1 = 0.f, s2 = 0.f, s3 = 0.f;
                #pragma unroll
                for (int t = 0; t < 16; t++) {
                    float4 kv = kr[t];
                    s0 += Q[4*t]   * kv.x; s1 += Q[4*t+1] * kv.y;
                    s2 += Q[4*t+2] * kv.z; s3 += Q[4*t+3] * kv.w;
                }
                float s = ((s0 + s1) + (s2 + s3)) * 0.125f;   // 1/sqrt(64)
                if (s > m) {
                    float corr = __expf(m - s);
                    l *= corr;
                    #pragma unroll
                    for (int j = 0; j < 64; j++) O[j] *= corr;
                    m = s;
                }
                float p = __expf(s - m);
                l += p;
                const float4* vr = (const float4*)&Vs[cc][0];
                #pragma unroll
                for (int t = 0; t < 16; t++) {
                    float4 vv = vr[t];
                    O[4*t]   += p * vv.x; O[4*t+1] += p * vv.y;
                    O[4*t+2] += p * vv.z; O[4*t+3] += p * vv.w;
                }
            }
        }
        __syncthreads();
    }
    float inv = (l > 0.f) ? (1.f / l) : 0.f;
    float4* op = (float4*)(g_att + (size_t)qrow * HIDDEN + head * HD);
    #pragma unroll
    for (int i = 0; i < 16; i++)
        op[i] = make_float4(O[4*i]*inv, O[4*i+1]*inv, O[4*i+2]*inv, O[4*i+3]*inv);
}

// ---------------- BatchNorm (batch stats) + ReLU -----------------------------
__global__ void bn_partial_kernel() {
    int c = threadIdx.x;         // 512
    int g = blockIdx.x;          // 48 row-groups of 128
    float s = 0.f, q = 0.f;
    const float* p = g_h + (size_t)g * 128 * HIDDEN + c;
    #pragma unroll 4
    for (int r = 0; r < 128; r++) {
        float x = p[(size_t)r * HIDDEN];
        s += x; q += x * x;
    }
    g_ps[g * HIDDEN + c] = s;
    g_pq[g * HIDDEN + c] = q;
}

__global__ void bn_final_kernel(const float* __restrict__ gamma, const float* __restrict__ beta) {
    int c = threadIdx.x;         // 512
    float s = 0.f, q = 0.f;
    #pragma unroll
    for (int g = 0; g < 48; g++) { s += g_ps[g * HIDDEN + c]; q += g_pq[g * HIDDEN + c]; }
    const float invN = 1.f / (float)NTOT;
    float mu  = s * invN;
    float var = q * invN - mu * mu;
    float sc  = gamma[c] * rsqrtf(var + 1e-5f);
    g_scale[c] = sc;
    g_shift[c] = beta[c] - mu * sc;
}

__global__ void bn_apply_kernel(float4* __restrict__ out) {
    int i = blockIdx.x * blockDim.x + threadIdx.x;   // over NTOT*HIDDEN/4
    float4 hv = ((const float4*)g_h)[i];
    int c = (i * 4) & (HIDDEN - 1);
    float4 r;
    r.x = fmaxf(0.f, hv.x * g_scale[c+0] + g_shift[c+0]);
    r.y = fmaxf(0.f, hv.y * g_scale[c+1] + g_shift[c+1]);
    r.z = fmaxf(0.f, hv.z * g_scale[c+2] + g_shift[c+2]);
    r.w = fmaxf(0.f, hv.w * g_scale[c+3] + g_shift[c+3]);
    out[i] = r;
}

// ---------------- launch ------------------------------------------------------
extern "C" void kernel_launch(void* const* d_in, const int* in_sizes, int n_in,
                              void* d_out, int out_size)
{
    const float* c_feat = (const float*)d_in[0];
    const float* d_feat = (const float*)d_in[1];
    const int*   cd     = (const int*)  d_in[2];
    const float* Wq = (const float*)d_in[3];  const float* bq = (const float*)d_in[4];
    const float* Wk = (const float*)d_in[5];  const float* bk = (const float*)d_in[6];
    const float* Wv = (const float*)d_in[7];  const float* bv = (const float*)d_in[8];
    const float* Wu = (const float*)d_in[9];  const float* bu = (const float*)d_in[10];
    const float* gamma = (const float*)d_in[11];
    const float* beta  = (const float*)d_in[12];
    float* out = (float*)d_out;

    copy_x_kernel<<<(NTOT*HIDDEN/4 + 255)/256, 256>>>((const float4*)c_feat, (const float4*)d_feat);
    pack_adj_kernel <<<(NC*(ND/32) + 255)/256, 256>>>(cd);
    pack_adjT_kernel<<<(ND*(NC/32) + 255)/256, 256>>>(cd);

    dim3 ggrid(HIDDEN/64, NTOT/128);
    gemm_kernel<<<ggrid, 256>>>(Wq, bq, 0, 512);
    gemm_kernel<<<ggrid, 256>>>(Wk, bk, 1, 512);
    gemm_kernel<<<ggrid, 256>>>(Wv, bv, 2, 512);

    attn_kernel<<<dim3(48, NHEAD), 128>>>();

    gemm_kernel<<<ggrid, 256>>>(Wu, bu, 3, 1024);

    bn_partial_kernel<<<48, 512>>>();
    bn_final_kernel<<<1, 512>>>(gamma, beta);
    bn_apply_kernel<<<(NTOT*HIDDEN/4 + 255)/256, 256>>>((float4*)out);
}

// round 2
// speedup vs baseline: 1.0020x; 1.0020x over previous
#include <cuda_runtime.h>

#define NC   4096
#define ND   2048
#define NTOT 6144
#define HIDDEN 512
#define NHEAD 8
#define HD   64

// ---------------- scratch (device globals: no allocations allowed) ----------
__device__ float g_x  [NTOT*HIDDEN];
__device__ float g_q  [NTOT*HIDDEN];
__device__ float g_k  [NTOT*HIDDEN];
__device__ float g_v  [NTOT*HIDDEN];
__device__ float g_att[NTOT*HIDDEN];
__device__ float g_h  [NTOT*HIDDEN];
__device__ unsigned g_adj [NC*(ND/32)];   // bit j of word: cd[i][w*32+j]
__device__ unsigned g_adjT[ND*(NC/32)];   // transposed bitmask for d-side queries
__device__ float g_ps[48*HIDDEN];
__device__ float g_pq[48*HIDDEN];
__device__ float g_scale[HIDDEN];
__device__ float g_shift[HIDDEN];

// ---------------- build x = concat(c, d) ------------------------------------
__global__ void copy_x_kernel(const float4* __restrict__ c, const float4* __restrict__ d) {
    int i = blockIdx.x * blockDim.x + threadIdx.x;   // over NTOT*HIDDEN/4
    const int nc4 = NC * HIDDEN / 4;
    float4* x4 = (float4*)g_x;
    if (i < nc4) x4[i] = c[i];
    else         x4[i] = d[i - nc4];
}

// ---------------- pack adjacency into bitmasks -------------------------------
__global__ void pack_adj_kernel(const int* __restrict__ cd) {
    int t = blockIdx.x * blockDim.x + threadIdx.x;   // over NC*(ND/32)
    if (t >= NC * (ND/32)) return;
    int i = t >> 6, w = t & 63;
    const int* p = cd + (size_t)i * ND + w * 32;
    unsigned bits = 0;
    #pragma unroll
    for (int b = 0; b < 32; b++) bits |= (p[b] != 0) ? (1u << b) : 0u;
    g_adj[t] = bits;
}

__global__ void pack_adjT_kernel(const int* __restrict__ cd) {
    int t = blockIdx.x * blockDim.x + threadIdx.x;   // over ND*(NC/32)
    if (t >= ND * (NC/32)) return;
    int w = t >> 11;          // which 32-block of c-side indices (0..127)
    int j = t & 2047;         // d-side index (coalesced across threads)
    unsigned bits = 0;
    #pragma unroll
    for (int b = 0; b < 32; b++)
        bits |= (cd[(size_t)(w * 32 + b) * ND + j] != 0) ? (1u << b) : 0u;
    g_adjT[(size_t)j * (NC/32) + w] = bits;
}

// ---------------- fp32 tiled GEMM: C = A @ W + bias --------------------------
// A rows come from g_x (k<512) or g_att (k>=512, for the concat GEMM).
// outSel: 0->g_q 1->g_k 2->g_v 3->g_h.  M=6144, N=512 fixed, K=Ktot.
__global__ void __launch_bounds__(256)
gemm_kernel(const float* __restrict__ W, const float* __restrict__ bias,
            int outSel, int Ktot)
{
    __shared__ float As[16][128];
    __shared__ float Bs[16][64];
    float* C = (outSel == 0) ? g_q : (outSel == 1) ? g_k : (outSel == 2) ? g_v : g_h;

    int tid = threadIdx.x;
    int tx = tid & 15, ty = tid >> 4;
    int rowBase = blockIdx.y * 128;
    int colBase = blockIdx.x * 64;

    float acc[8][4];
    #pragma unroll
    for (int i = 0; i < 8; i++)
        #pragma unroll
        for (int j = 0; j < 4; j++) acc[i][j] = 0.f;

    for (int k0 = 0; k0 < Ktot; k0 += 16) {
        // load A tile 128x16 (512 float4s)
        #pragma unroll
        for (int l = 0; l < 2; l++) {
            int f = tid + l * 256;
            int r = f >> 2, c4 = f & 3;
            int kk = k0 + c4 * 4;
            const float* src = (kk < HIDDEN)
                ? (g_x   + (size_t)(rowBase + r) * HIDDEN + kk)
                : (g_att + (size_t)(rowBase + r) * HIDDEN + (kk - HIDDEN));
            float4 val = *(const float4*)src;
            As[c4*4+0][r] = val.x; As[c4*4+1][r] = val.y;
            As[c4*4+2][r] = val.z; As[c4*4+3][r] = val.w;
        }
        // load B tile 16x64 (256 float4s)
        {
            int r = tid >> 4, c4 = tid & 15;
            float4 val = *(const float4*)(W + (size_t)(k0 + r) * HIDDEN + colBase + c4 * 4);
            *(float4*)&Bs[r][c4*4] = val;
        }
        __syncthreads();
        #pragma unroll
        for (int kk = 0; kk < 16; kk++) {
            float a[8], b[4];
            #pragma unroll
            for (int i = 0; i < 8; i++) a[i] = As[kk][ty*8 + i];
            #pragma unroll
            for (int j = 0; j < 4; j++) b[j] = Bs[kk][tx*4 + j];
            #pragma unroll
            for (int i = 0; i < 8; i++)
                #pragma unroll
                for (int j = 0; j < 4; j++) acc[i][j] += a[i] * b[j];
        }
        __syncthreads();
    }
    #pragma unroll
    for (int i = 0; i < 8; i++) {
        int row = rowBase + ty*8 + i;
        #pragma unroll
        for (int j = 0; j < 4; j++) {
            int col = colBase + tx*4 + j;
            C[(size_t)row * HIDDEN + col] = acc[i][j] + bias[col];
        }
    }
}

// ---------------- flash attention with bitmask skip --------------------------
// grid: (48 query tiles of 128, 8 heads). 1 thread = 1 query row.
// c-side queries (tiles 0..31) attend only d-side keys; vice versa.
__global__ void __launch_bounds__(128, 2)
attn_kernel()
{
    __shared__ float Ks[64][64];
    __shared__ float Vs[64][64];
    int head = blockIdx.y;
    int tid  = threadIdx.x;
    int qt   = blockIdx.x;
    bool cside = (qt < 32);
    int qrow  = cside ? qt * 128 + tid : NC + (qt - 32) * 128 + tid;
    int kbase = cside ? NC : 0;
    int nkeys = cside ? ND : NC;
    const unsigned* mrow = cside ? (g_adj  + (size_t)qrow * (ND/32))
                                 : (g_adjT + (size_t)(qrow - NC) * (NC/32));

    float Q[64], O[64];
    {
        const float4* qp = (const float4*)(g_q + (size_t)qrow * HIDDEN + head * HD);
        #pragma unroll
        for (int i = 0; i < 16; i++) {
            float4 t = qp[i];
            Q[4*i] = t.x; Q[4*i+1] = t.y; Q[4*i+2] = t.z; Q[4*i+3] = t.w;
        }
    }
    #pragma unroll
    for (int i = 0; i < 64; i++) O[i] = 0.f;
    float m = -1e30f, l = 0.f;

    #pragma unroll 1
    for (int kb = 0; kb < nkeys; kb += 64) {
        #pragma unroll
        for (int i = 0; i < 8; i++) {
            int f = tid + 128 * i;
            int r = f >> 4, c4 = f & 15;
            const float4* ks = (const float4*)(g_k + (size_t)(kbase + kb + r) * HIDDEN + head * HD);
            const float4* vs = (const float4*)(g_v + (size_t)(kbase + kb + r) * HIDDEN + head * HD);
            ((float4*)&Ks[r][0])[c4] = ks[c4];
            ((float4*)&Vs[r][0])[c4] = vs[c4];
        }
        unsigned w0 = mrow[kb >> 5];
        unsigned w1 = mrow[(kb >> 5) + 1];
        __syncthreads();

        #pragma unroll 1
        for (int cc = 0; cc < 64; cc++) {
            unsigned bit = ((cc < 32 ? (w0 >> cc) : (w1 >> (cc - 32))) & 1u);
            if (bit) {
                const float4* kr = (const float4*)&Ks[cc][0];
                float s0 = 0.f, s1 = 0.f, s2 = 0.f, s3 = 0.f;
                #pragma unroll
                for (int t = 0; t < 16; t++) {
                    float4 kv = kr[t];
                    s0 += Q[4*t]   * kv.x; s1 += Q[4*t+1] * kv.y;
                    s2 += Q[4*t+2] * kv.z; s3 += Q[4*t+3] * kv.w;
                }
                float s = ((s0 + s1) + (s2 + s3)) * 0.125f;   // 1/sqrt(64)
                if (s > m) {
                    float corr = __expf(m - s);
                    l *= corr;
                    #pragma unroll
                    for (int j = 0; j < 64; j++) O[j] *= corr;
                    m = s;
                }
                float p = __expf(s - m);
                l += p;
                const float4* vr = (const float4*)&Vs[cc][0];
                #pragma unroll
                for (int t = 0; t < 16; t++) {
                    float4 vv = vr[t];
                    O[4*t]   += p * vv.x; O[4*t+1] += p * vv.y;
                    O[4*t+2] += p * vv.z; O[4*t+3] += p * vv.w;
                }
            }
        }
        __syncthreads();
    }
    float inv = (l > 0.f) ? (1.f / l) : 0.f;
    float4* op = (float4*)(g_att + (size_t)qrow * HIDDEN + head * HD);
    #pragma unroll
    for (int i = 0; i < 16; i++)
        op[i] = make_float4(O[4*i]*inv, O[4*i+1]*inv, O[4*i+2]*inv, O[4*i+3]*inv);
}

// ---------------- BatchNorm (batch stats) + ReLU -----------------------------
__global__ void bn_partial_kernel() {
    int c = threadIdx.x;         // 512
    int g = blockIdx.x;          // 48 row-groups of 128
    float s = 0.f, q = 0.f;
    const float* p = g_h + (size_t)g * 128 * HIDDEN + c;
    #pragma unroll 4
    for (int r = 0; r < 128; r++) {
        float x = p[(size_t)r * HIDDEN];
        s += x; q += x * x;
    }
    g_ps[g * HIDDEN + c] = s;
    g_pq[g * HIDDEN + c] = q;
}

__global__ void bn_final_kernel(const float* __restrict__ gamma, const float* __restrict__ beta) {
    int c = threadIdx.x;         // 512
    float s = 0.f, q = 0.f;
    #pragma unroll
    for (int g = 0; g < 48; g++) { s += g_ps[g * HIDDEN + c]; q += g_pq[g * HIDDEN + c]; }
    const float invN = 1.f / (float)NTOT;
    float mu  = s * invN;
    float var = q * invN - mu * mu;
    float sc  = gamma[c] * rsqrtf(var + 1e-5f);
    g_scale[c] = sc;
    g_shift[c] = beta[c] - mu * sc;
}

__global__ void bn_apply_kernel(float4* __restrict__ out) {
    int i = blockIdx.x * blockDim.x + threadIdx.x;   // over NTOT*HIDDEN/4
    float4 hv = ((const float4*)g_h)[i];
    int c = (i * 4) & (HIDDEN - 1);
    float4 r;
    r.x = fmaxf(0.f, hv.x * g_scale[c+0] + g_shift[c+0]);
    r.y = fmaxf(0.f, hv.y * g_scale[c+1] + g_shift[c+1]);
    r.z = fmaxf(0.f, hv.z * g_scale[c+2] + g_shift[c+2]);
    r.w = fmaxf(0.f, hv.w * g_scale[c+3] + g_shift[c+3]);
    out[i] = r;
}

// ---------------- launch ------------------------------------------------------
extern "C" void kernel_launch(void* const* d_in, const int* in_sizes, int n_in,
                              void* d_out, int out_size)
{
    const float* c_feat = (const float*)d_in[0];
    const float* d_feat = (const float*)d_in[1];
    const int*   cd     = (const int*)  d_in[2];
    const float* Wq = (const float*)d_in[3];  const float* bq = (const float*)d_in[4];
    const float* Wk = (const float*)d_in[5];  const float* bk = (const float*)d_in[6];
    const float* Wv = (const float*)d_in[7];  const float* bv = (const float*)d_in[8];
    const float* Wu = (const float*)d_in[9];  const float* bu = (const float*)d_in[10];
    const float* gamma = (const float*)d_in[11];
    const float* beta  = (const float*)d_in[12];
    float* out = (float*)d_out;

    copy_x_kernel<<<(NTOT*HIDDEN/4 + 255)/256, 256>>>((const float4*)c_feat, (const float4*)d_feat);
    pack_adj_kernel <<<(NC*(ND/32) + 255)/256, 256>>>(cd);
    pack_adjT_kernel<<<(ND*(NC/32) + 255)/256, 256>>>(cd);

    dim3 ggrid(HIDDEN/64, NTOT/128);
    gemm_kernel<<<ggrid, 256>>>(Wq, bq, 0, 512);
    gemm_kernel<<<ggrid, 256>>>(Wk, bk, 1, 512);
    gemm_kernel<<<ggrid, 256>>>(Wv, bv, 2, 512);

    attn_kernel<<<dim3(48, NHEAD), 128>>>();

    gemm_kernel<<<ggrid, 256>>>(Wu, bu, 3, 1024);

    bn_partial_kernel<<<48, 512>>>();
    bn_final_kernel<<<1, 512>>>(gamma, beta);
    bn_apply_kernel<<<(NTOT*HIDDEN/4 + 255)/256, 256>>>((float4*)out);
}

// round 4
// speedup vs baseline: 2.2827x; 2.2782x over previous
#include <cuda_runtime.h>
#include <cstdint>

#define NC   4096
#define ND   2048
#define NTOT 6144
#define HIDDEN 512
#define NHEAD 8
#define HD   64
#define PAD  72

__device__ float g_x  [NTOT*HIDDEN];
__device__ float g_q  [NTOT*HIDDEN];
__device__ float g_k  [NTOT*HIDDEN];
__device__ float g_v  [NTOT*HIDDEN];
__device__ float g_kT [HIDDEN*NTOT];     // [hd][row]
__device__ float g_att[NTOT*HIDDEN];
__device__ float g_h  [NTOT*HIDDEN];
__device__ unsigned g_adj [NC*(ND/32)];
__device__ unsigned g_adjT[ND*(NC/32)];
__device__ float g_qn  [NTOT*NHEAD];
__device__ float g_kmax[2*NHEAD];
__device__ float g_ps[48*HIDDEN];
__device__ float g_pq[48*HIDDEN];
__device__ float g_scale[HIDDEN];
__device__ float g_shift[HIDDEN];

// ---------------- mma helpers -------------------------------------------------
__device__ __forceinline__ uint32_t s2u(const void* p) {
    uint32_t a;
    asm("{ .reg .u64 t; cvta.to.shared.u64 t, %1; cvt.u32.u64 %0, t; }" : "=r"(a) : "l"(p));
    return a;
}
__device__ __forceinline__ void mma_tf32(float* d, const unsigned* a, const unsigned* b) {
    asm volatile("mma.sync.aligned.m16n8k8.row.col.f32.tf32.tf32.f32 "
        "{%0,%1,%2,%3}, {%4,%5,%6,%7}, {%8,%9}, {%0,%1,%2,%3};"
        : "+f"(d[0]), "+f"(d[1]), "+f"(d[2]), "+f"(d[3])
        : "r"(a[0]), "r"(a[1]), "r"(a[2]), "r"(a[3]), "r"(b[0]), "r"(b[1]));
}
__device__ __forceinline__ void ldmA(unsigned* a, uint32_t addr) {
    asm volatile("ldmatrix.sync.aligned.m8n8.x4.shared.b16 {%0,%1,%2,%3}, [%4];"
        : "=r"(a[0]), "=r"(a[1]), "=r"(a[2]), "=r"(a[3]) : "r"(addr));
}
__device__ __forceinline__ float tf32hi(float x) {
    uint32_t h; asm("cvt.rna.tf32.f32 %0, %1;" : "=r"(h) : "f"(x));
    return __uint_as_float(h);
}

// ---------------- prep kernels -----------------------------------------------
__global__ void copy_x_kernel(const float4* __restrict__ c, const float4* __restrict__ d) {
    int i = blockIdx.x * blockDim.x + threadIdx.x;
    const int nc4 = NC * HIDDEN / 4;
    float4* x4 = (float4*)g_x;
    if (i < nc4) x4[i] = c[i]; else x4[i] = d[i - nc4];
}
__global__ void pack_adj_kernel(const int* __restrict__ cd) {
    int t = blockIdx.x * blockDim.x + threadIdx.x;
    if (t >= NC * (ND/32)) return;
    int i = t >> 6, w = t & 63;
    const int* p = cd + (size_t)i * ND + w * 32;
    unsigned bits = 0;
    #pragma unroll
    for (int b = 0; b < 32; b++) bits |= (p[b] != 0) ? (1u << b) : 0u;
    g_adj[t] = bits;
}
__global__ void pack_adjT_kernel(const int* __restrict__ cd) {
    int t = blockIdx.x * blockDim.x + threadIdx.x;
    if (t >= ND * (NC/32)) return;
    int w = t >> 11, j = t & 2047;
    unsigned bits = 0;
    #pragma unroll
    for (int b = 0; b < 32; b++)
        bits |= (cd[(size_t)(w * 32 + b) * ND + j] != 0) ? (1u << b) : 0u;
    g_adjT[(size_t)j * (NC/32) + w] = bits;
}
// g_kT[col][row] = g_k[row][col], R=NTOT rows, C=512 cols
__global__ void transpose_k_kernel() {
    __shared__ float t[32][33];
    int bx = blockIdx.x * 32, by = blockIdx.y * 32;
    int x = bx + threadIdx.x, y = by + threadIdx.y;
    #pragma unroll
    for (int i = 0; i < 32; i += 8) t[threadIdx.y + i][threadIdx.x] = g_k[(size_t)(y + i) * HIDDEN + x];
    __syncthreads();
    x = by + threadIdx.x; y = bx + threadIdx.y;
    #pragma unroll
    for (int i = 0; i < 32; i += 8) g_kT[(size_t)(y + i) * NTOT + x] = t[threadIdx.x][threadIdx.y + i];
}
__global__ void qn_kernel() {
    int idx = blockIdx.x * blockDim.x + threadIdx.x;
    if (idx >= NTOT * NHEAD) return;
    int row = idx >> 3, h = idx & 7;
    const float4* p = (const float4*)(g_q + (size_t)row * HIDDEN + h * HD);
    float s = 0.f;
    #pragma unroll
    for (int i = 0; i < 16; i++) { float4 v = p[i]; s += v.x*v.x + v.y*v.y + v.z*v.z + v.w*v.w; }
    g_qn[idx] = sqrtf(s);
}
__global__ void kmax_kernel() {
    int head = blockIdx.x, side = blockIdx.y;
    int r0 = side ? NC : 0, nr = side ? ND : NC;
    int tid = threadIdx.x;
    float mx = 0.f;
    for (int r = tid; r < nr; r += 256) {
        const float4* p = (const float4*)(g_k + (size_t)(r0 + r) * HIDDEN + head * HD);
        float s = 0.f;
        #pragma unroll
        for (int i = 0; i < 16; i++) { float4 v = p[i]; s += v.x*v.x + v.y*v.y + v.z*v.z + v.w*v.w; }
        mx = fmaxf(mx, s);
    }
    __shared__ float red[256];
    red[tid] = mx; __syncthreads();
    for (int o = 128; o; o >>= 1) { if (tid < o) red[tid] = fmaxf(red[tid], red[tid + o]); __syncthreads(); }
    if (tid == 0) g_kmax[side * 8 + head] = sqrtf(red[0]);
}

// ---------------- SIMT GEMM (proven): C = A @ W + bias -----------------------
__global__ void __launch_bounds__(256)
gemm_kernel(const float* __restrict__ W, const float* __restrict__ bias,
            int outSel, int Ktot)
{
    __shared__ float As[16][128];
    __shared__ float Bs[16][64];
    float* C = (outSel == 0) ? g_q : (outSel == 1) ? g_k : (outSel == 2) ? g_v : g_h;

    int tid = threadIdx.x;
    int tx = tid & 15, ty = tid >> 4;
    int rowBase = blockIdx.y * 128;
    int colBase = blockIdx.x * 64;

    float acc[8][4];
    #pragma unroll
    for (int i = 0; i < 8; i++)
        #pragma unroll
        for (int j = 0; j < 4; j++) acc[i][j] = 0.f;

    for (int k0 = 0; k0 < Ktot; k0 += 16) {
        #pragma unroll
        for (int l = 0; l < 2; l++) {
            int f = tid + l * 256;
            int r = f >> 2, c4 = f & 3;
            int kk = k0 + c4 * 4;
            const float* src = (kk < HIDDEN)
                ? (g_x   + (size_t)(rowBase + r) * HIDDEN + kk)
                : (g_att + (size_t)(rowBase + r) * HIDDEN + (kk - HIDDEN));
            float4 val = *(const float4*)src;
            As[c4*4+0][r] = val.x; As[c4*4+1][r] = val.y;
            As[c4*4+2][r] = val.z; As[c4*4+3][r] = val.w;
        }
        {
            int r = tid >> 4, c4 = tid & 15;
            float4 val = *(const float4*)(W + (size_t)(k0 + r) * HIDDEN + colBase + c4 * 4);
            *(float4*)&Bs[r][c4*4] = val;
        }
        __syncthreads();
        #pragma unroll
        for (int kk = 0; kk < 16; kk++) {
            float a[8], b[4];
            #pragma unroll
            for (int i = 0; i < 8; i++) a[i] = As[kk][ty*8 + i];
            #pragma unroll
            for (int j = 0; j < 4; j++) b[j] = Bs[kk][tx*4 + j];
            #pragma unroll
            for (int i = 0; i < 8; i++)
                #pragma unroll
                for (int j = 0; j < 4; j++) acc[i][j] += a[i] * b[j];
        }
        __syncthreads();
    }
    #pragma unroll
    for (int i = 0; i < 8; i++) {
        int row = rowBase + ty*8 + i;
        #pragma unroll
        for (int j = 0; j < 4; j++) {
            int col = colBase + tx*4 + j;
            C[(size_t)row * HIDDEN + col] = acc[i][j] + bias[col];
        }
    }
}

// ---------------- mma.sync flash attention ------------------------------------
// grid (48, 8): qt<16 d-side queries, else c-side. 256 thr, warp w: 16 q rows.
__global__ void __launch_bounds__(256, 1)
attn_mma()
{
    extern __shared__ float sm[];
    float* Qhi  = sm;                    // [128][PAD]
    float* Qlo  = Qhi  + 128*PAD;
    float* KThi = Qlo  + 128*PAD;        // [64 d][PAD keys]
    float* KTlo = KThi + 64*PAD;
    float* Vhi  = KTlo + 64*PAD;         // [64 key][PAD d]
    float* Pm   = Vhi  + 64*PAD;         // [128][PAD]
    unsigned* Mw = (unsigned*)(Pm + 128*PAD);   // [128][2]

    const int tid = threadIdx.x, lane = tid & 31, w = tid >> 5;
    const int qt = blockIdx.x, head = blockIdx.y;
    const bool dside = (qt < 16);
    const int qbase = dside ? NC + qt * 128 : (qt - 16) * 128;
    const int kbase = dside ? 0 : NC;
    const int nkeys = dside ? NC : ND;
    const int qr0 = w * 16;

    // load Q tile, split hi/lo
    #pragma unroll
    for (int i = 0; i < 8; i++) {
        int f = tid + i * 256;
        int r = f >> 4, c = (f & 15) * 4;
        float4 v = *(const float4*)(g_q + (size_t)(qbase + r) * HIDDEN + head * HD + c);
        float hx = tf32hi(v.x), hy = tf32hi(v.y), hz = tf32hi(v.z), hw = tf32hi(v.w);
        float* qh = Qhi + r * PAD + c;
        float* ql = Qlo + r * PAD + c;
        qh[0] = hx; qh[1] = hy; qh[2] = hz; qh[3] = hw;
        ql[0] = v.x - hx; ql[1] = v.y - hy; ql[2] = v.z - hz; ql[3] = v.w - hw;
    }
    __syncthreads();

    const int rA = qr0 + (lane >> 2), rB = rA + 8;
    const float kmx = g_kmax[(dside ? 0 : 8) + head];
    const float MqA = g_qn[(qbase + rA) * NHEAD + head] * kmx * 0.125f;
    const float MqB = g_qn[(qbase + rB) * NHEAD + head] * kmx * 0.125f;
    const unsigned* mb = dside ? g_adjT + (size_t)(qbase - NC + tid) * (NC/32)
                               : g_adj  + (size_t)(qbase + tid) * (ND/32);

    const uint32_t aoff = (uint32_t)(((qr0 + (lane & 15)) * PAD + (lane >> 4) * 4) * 4);
    const uint32_t addrQhi = s2u(Qhi) + aoff;
    const uint32_t addrQlo = s2u(Qlo) + aoff;
    const uint32_t addrP   = s2u(Pm)  + aoff;
    const unsigned* KThi_u = (const unsigned*)KThi;
    const unsigned* KTlo_u = (const unsigned*)KTlo;
    const unsigned* Vhi_u  = (const unsigned*)Vhi;
    const int boff0 = (lane & 3) * PAD + (lane >> 2);

    float oacc[8][4];
    #pragma unroll
    for (int n = 0; n < 8; n++)
        #pragma unroll
        for (int j = 0; j < 4; j++) oacc[n][j] = 0.f;
    float lA = 0.f, lB = 0.f;

    #pragma unroll 1
    for (int kb = 0; kb < nkeys; kb += 64) {
        // load KT tile (rows=d, cols=key), split hi/lo
        #pragma unroll
        for (int i = 0; i < 4; i++) {
            int f = tid + i * 256;
            int d = f >> 4, c = (f & 15) * 4;
            float4 v = *(const float4*)(g_kT + (size_t)(head * HD + d) * NTOT + kbase + kb + c);
            float hx = tf32hi(v.x), hy = tf32hi(v.y), hz = tf32hi(v.z), hw = tf32hi(v.w);
            float* kh = KThi + d * PAD + c;
            float* kl = KTlo + d * PAD + c;
            kh[0] = hx; kh[1] = hy; kh[2] = hz; kh[3] = hw;
            kl[0] = v.x - hx; kl[1] = v.y - hy; kl[2] = v.z - hz; kl[3] = v.w - hw;
        }
        // load V tile (rows=key, cols=d), single precision (tf32-truncated by mma)
        #pragma unroll
        for (int i = 0; i < 4; i++) {
            int f = tid + i * 256;
            int k = f >> 4, c = (f & 15) * 4;
            float4 v = *(const float4*)(g_v + (size_t)(kbase + kb + k) * HIDDEN + head * HD + c);
            float* vp = Vhi + k * PAD + c;
            vp[0] = v.x; vp[1] = v.y; vp[2] = v.z; vp[3] = v.w;
        }
        if (tid < 128) {
            Mw[tid * 2]     = mb[(kb >> 5)];
            Mw[tid * 2 + 1] = mb[(kb >> 5) + 1];
        }
        __syncthreads();

        // ---- S = Q K^T (tf32 x3) ----
        float sacc[8][4];
        #pragma unroll
        for (int n = 0; n < 8; n++)
            #pragma unroll
            for (int j = 0; j < 4; j++) sacc[n][j] = 0.f;
        #pragma unroll
        for (int ks = 0; ks < 8; ks++) {
            unsigned ahi[4], alo[4];
            ldmA(ahi, addrQhi + ks * 32);
            ldmA(alo, addrQlo + ks * 32);
            int bb = ks * 8 * PAD + boff0;
            #pragma unroll
            for (int n = 0; n < 8; n++) {
                unsigned bh[2], bl[2];
                bh[0] = KThi_u[bb + n * 8];
                bh[1] = KThi_u[bb + 4 * PAD + n * 8];
                bl[0] = KTlo_u[bb + n * 8];
                bl[1] = KTlo_u[bb + 4 * PAD + n * 8];
                mma_tf32(sacc[n], ahi, bh);
                mma_tf32(sacc[n], ahi, bl);
                mma_tf32(sacc[n], alo, bh);
            }
        }
        // ---- softmax epilogue (single pass, bound-shifted) ----
        #pragma unroll
        for (int n = 0; n < 8; n++) {
            int colb = n * 8 + 2 * (lane & 3);
            unsigned mwA = Mw[(qr0 + (lane >> 2)) * 2 + (colb >> 5)];
            unsigned mwB = Mw[(qr0 + (lane >> 2) + 8) * 2 + (colb >> 5)];
            int bit = colb & 31;
            float p0 = ((mwA >> bit) & 1u)       ? __expf(sacc[n][0] * 0.125f - MqA) : 0.f;
            float p1 = ((mwA >> (bit + 1)) & 1u) ? __expf(sacc[n][1] * 0.125f - MqA) : 0.f;
            float p2 = ((mwB >> bit) & 1u)       ? __expf(sacc[n][2] * 0.125f - MqB) : 0.f;
            float p3 = ((mwB >> (bit + 1)) & 1u) ? __expf(sacc[n][3] * 0.125f - MqB) : 0.f;
            lA += p0 + p1; lB += p2 + p3;
            *(float2*)(Pm + rA * PAD + colb) = make_float2(p0, p1);
            *(float2*)(Pm + rB * PAD + colb) = make_float2(p2, p3);
        }
        __syncwarp();
        // ---- O += P V (single tf32) ----
        #pragma unroll
        for (int ks = 0; ks < 8; ks++) {
            unsigned ap[4];
            ldmA(ap, addrP + ks * 32);
            int bb = ks * 8 * PAD + boff0;
            #pragma unroll
            for (int n = 0; n < 8; n++) {
                unsigned bv[2];
                bv[0] = Vhi_u[bb + n * 8];
                bv[1] = Vhi_u[bb + 4 * PAD + n * 8];
                mma_tf32(oacc[n], ap, bv);
            }
        }
        __syncthreads();
    }

    lA += __shfl_xor_sync(0xFFFFFFFFu, lA, 1);
    lA += __shfl_xor_sync(0xFFFFFFFFu, lA, 2);
    lB += __shfl_xor_sync(0xFFFFFFFFu, lB, 1);
    lB += __shfl_xor_sync(0xFFFFFFFFu, lB, 2);
    float invA = (lA > 0.f) ? 1.f / lA : 0.f;
    float invB = (lB > 0.f) ? 1.f / lB : 0.f;

    #pragma unroll
    for (int n = 0; n < 8; n++) {
        int colb = head * HD + n * 8 + 2 * (lane & 3);
        *(float2*)(g_att + (size_t)(qbase + rA) * HIDDEN + colb) =
            make_float2(oacc[n][0] * invA, oacc[n][1] * invA);
        *(float2*)(g_att + (size_t)(qbase + rB) * HIDDEN + colb) =
            make_float2(oacc[n][2] * invB, oacc[n][3] * invB);
    }
}

// ---------------- BatchNorm + ReLU -------------------------------------------
__global__ void bn_partial_kernel() {
    int c = threadIdx.x, g = blockIdx.x;
    float s = 0.f, q = 0.f;
    const float* p = g_h + (size_t)g * 128 * HIDDEN + c;
    #pragma unroll 4
    for (int r = 0; r < 128; r++) { float x = p[(size_t)r * HIDDEN]; s += x; q += x * x; }
    g_ps[g * HIDDEN + c] = s;
    g_pq[g * HIDDEN + c] = q;
}
__global__ void bn_final_kernel(const float* __restrict__ gamma, const float* __restrict__ beta) {
    int c = threadIdx.x;
    float s = 0.f, q = 0.f;
    #pragma unroll
    for (int g = 0; g < 48; g++) { s += g_ps[g * HIDDEN + c]; q += g_pq[g * HIDDEN + c]; }
    const float invN = 1.f / (float)NTOT;
    float mu = s * invN, var = q * invN - mu * mu;
    float sc = gamma[c] * rsqrtf(var + 1e-5f);
    g_scale[c] = sc; g_shift[c] = beta[c] - mu * sc;
}
__global__ void bn_apply_kernel(float4* __restrict__ out) {
    int i = blockIdx.x * blockDim.x + threadIdx.x;
    float4 hv = ((const float4*)g_h)[i];
    int c = (i * 4) & (HIDDEN - 1);
    out[i] = make_float4(fmaxf(0.f, hv.x * g_scale[c]   + g_shift[c]),
                         fmaxf(0.f, hv.y * g_scale[c+1] + g_shift[c+1]),
                         fmaxf(0.f, hv.z * g_scale[c+2] + g_shift[c+2]),
                         fmaxf(0.f, hv.w * g_scale[c+3] + g_shift[c+3]));
}

// ---------------- launch ------------------------------------------------------
extern "C" void kernel_launch(void* const* d_in, const int* in_sizes, int n_in,
                              void* d_out, int out_size)
{
    const float* c_feat = (const float*)d_in[0];
    const float* d_feat = (const float*)d_in[1];
    const int*   cd     = (const int*)  d_in[2];
    const float* Wq = (const float*)d_in[3];  const float* bq = (const float*)d_in[4];
    const float* Wk = (const float*)d_in[5];  const float* bk = (const float*)d_in[6];
    const float* Wv = (const float*)d_in[7];  const float* bv = (const float*)d_in[8];
    const float* Wu = (const float*)d_in[9];  const float* bu = (const float*)d_in[10];
    const float* gamma = (const float*)d_in[11];
    const float* beta  = (const float*)d_in[12];
    float* out = (float*)d_out;

    const int ASM = (128*PAD*2 + 64*PAD*3 + 128*PAD) * 4 + 128 * 2 * 4;
    static int configured = -1;
    if (configured < 0) {
        cudaFuncSetAttribute(attn_mma, cudaFuncAttributeMaxDynamicSharedMemorySize, ASM);
        configured = 1;
    }

    copy_x_kernel<<<(NTOT*HIDDEN/4 + 255)/256, 256>>>((const float4*)c_feat, (const float4*)d_feat);
    pack_adj_kernel <<<(NC*(ND/32) + 255)/256, 256>>>(cd);
    pack_adjT_kernel<<<(ND*(NC/32) + 255)/256, 256>>>(cd);

    dim3 ggrid(HIDDEN/64, NTOT/128);
    gemm_kernel<<<ggrid, 256>>>(Wq, bq, 0, 512);
    gemm_kernel<<<ggrid, 256>>>(Wk, bk, 1, 512);
    gemm_kernel<<<ggrid, 256>>>(Wv, bv, 2, 512);

    transpose_k_kernel<<<dim3(HIDDEN/32, NTOT/32), dim3(32, 8)>>>();
    qn_kernel<<<(NTOT*NHEAD + 255)/256, 256>>>();
    kmax_kernel<<<dim3(NHEAD, 2), 256>>>();

    attn_mma<<<dim3(48, NHEAD), 256, ASM>>>();

    gemm_kernel<<<ggrid, 256>>>(Wu, bu, 3, 1024);

    bn_partial_kernel<<<48, 512>>>();
    bn_final_kernel<<<1, 512>>>(gamma, beta);
    bn_apply_kernel<<<(NTOT*HIDDEN/4 + 255)/256, 256>>>((float4*)out);
}

// round 5
// speedup vs baseline: 3.6671x; 1.6065x over previous
#include <cuda_runtime.h>
#include <cuda_fp16.h>
#include <cstdint>

#define NC   4096
#define ND   2048
#define NTOT 6144
#define HIDDEN 512
#define NHEAD 8
#define HD   64
#define PADH 72   // half-element row stride for smem tiles

__device__ float g_q  [NTOT*HIDDEN];
__device__ float g_k  [NTOT*HIDDEN];
__device__ float g_v  [NTOT*HIDDEN];
__device__ float g_vT [HIDDEN*NTOT];     // [hid][row]
__device__ float g_att[NTOT*HIDDEN];
__device__ float g_h  [NTOT*HIDDEN];
__device__ float g_WtQ[HIDDEN*HIDDEN];   // Wt[j][k] = W[k][j]
__device__ float g_WtK[HIDDEN*HIDDEN];
__device__ float g_WtV[HIDDEN*HIDDEN];
__device__ float g_WtU[HIDDEN*2*HIDDEN];
__device__ unsigned g_adj [NC*(ND/32)];
__device__ unsigned g_adjT[ND*(NC/32)];
__device__ float g_qn  [NTOT*NHEAD];
__device__ float g_kmax[2*NHEAD];
__device__ float g_ps[48*HIDDEN];
__device__ float g_pq[48*HIDDEN];
__device__ float g_scale[HIDDEN];
__device__ float g_shift[HIDDEN];

// ---------------- mma helpers -------------------------------------------------
__device__ __forceinline__ uint32_t s2u(const void* p) {
    uint32_t a;
    asm("{ .reg .u64 t; cvta.to.shared.u64 t, %1; cvt.u32.u64 %0, t; }" : "=r"(a) : "l"(p));
    return a;
}
__device__ __forceinline__ void mma_f16(float* d, const unsigned* a, const unsigned* b) {
    asm volatile("mma.sync.aligned.m16n8k16.row.col.f32.f16.f16.f32 "
        "{%0,%1,%2,%3}, {%4,%5,%6,%7}, {%8,%9}, {%0,%1,%2,%3};"
        : "+f"(d[0]), "+f"(d[1]), "+f"(d[2]), "+f"(d[3])
        : "r"(a[0]), "r"(a[1]), "r"(a[2]), "r"(a[3]), "r"(b[0]), "r"(b[1]));
}
__device__ __forceinline__ void ldmA(unsigned* a, uint32_t addr) {
    asm volatile("ldmatrix.sync.aligned.m8n8.x4.shared.b16 {%0,%1,%2,%3}, [%4];"
        : "=r"(a[0]), "=r"(a[1]), "=r"(a[2]), "=r"(a[3]) : "r"(addr));
}
// split float into f16 hi + f16 lo (lo = x - hi, exact in f16 range)
__device__ __forceinline__ void h_split(float x, __half& hi, __half& lo) {
    hi = __float2half_rn(x);
    lo = __float2half_rn(x - __half2float(hi));
}

// ---------------- prep kernels -----------------------------------------------
__global__ void pack_adj_kernel(const int* __restrict__ cd) {
    int t = blockIdx.x * blockDim.x + threadIdx.x;
    if (t >= NC * (ND/32)) return;
    int i = t >> 6, w = t & 63;
    const int* p = cd + (size_t)i * ND + w * 32;
    unsigned bits = 0;
    #pragma unroll
    for (int b = 0; b < 32; b++) bits |= (p[b] != 0) ? (1u << b) : 0u;
    g_adj[t] = bits;
}
__global__ void pack_adjT_kernel(const int* __restrict__ cd) {
    int t = blockIdx.x * blockDim.x + threadIdx.x;
    if (t >= ND * (NC/32)) return;
    int w = t >> 11, j = t & 2047;
    unsigned bits = 0;
    #pragma unroll
    for (int b = 0; b < 32; b++)
        bits |= (cd[(size_t)(w * 32 + b) * ND + j] != 0) ? (1u << b) : 0u;
    g_adjT[(size_t)j * (NC/32) + w] = bits;
}
// out[C][R] = in[R][C]; outSel: 0 WtQ 1 WtK 2 WtV 3 WtU 4 vT(in ignored, src=g_v)
__global__ void transpose_kernel(const float* __restrict__ in, int outSel, int R, int C) {
    __shared__ float t[32][33];
    float* out = (outSel == 0) ? g_WtQ : (outSel == 1) ? g_WtK : (outSel == 2) ? g_WtV
               : (outSel == 3) ? g_WtU : g_vT;
    const float* src = (outSel == 4) ? g_v : in;
    int bx = blockIdx.x * 32, by = blockIdx.y * 32;
    int x = bx + threadIdx.x, y = by + threadIdx.y;
    #pragma unroll
    for (int i = 0; i < 32; i += 8) t[threadIdx.y + i][threadIdx.x] = src[(size_t)(y + i) * C + x];
    __syncthreads();
    x = by + threadIdx.x; y = bx + threadIdx.y;
    #pragma unroll
    for (int i = 0; i < 32; i += 8) out[(size_t)(y + i) * R + x] = t[threadIdx.x][threadIdx.y + i];
}
__global__ void qn_kernel() {
    int idx = blockIdx.x * blockDim.x + threadIdx.x;
    if (idx >= NTOT * NHEAD) return;
    int row = idx >> 3, h = idx & 7;
    const float4* p = (const float4*)(g_q + (size_t)row * HIDDEN + h * HD);
    float s = 0.f;
    #pragma unroll
    for (int i = 0; i < 16; i++) { float4 v = p[i]; s += v.x*v.x + v.y*v.y + v.z*v.z + v.w*v.w; }
    g_qn[idx] = sqrtf(s);
}
__global__ void kmax_kernel() {
    int head = blockIdx.x, side = blockIdx.y;
    int r0 = side ? NC : 0, nr = side ? ND : NC;
    int tid = threadIdx.x;
    float mx = 0.f;
    for (int r = tid; r < nr; r += 256) {
        const float4* p = (const float4*)(g_k + (size_t)(r0 + r) * HIDDEN + head * HD);
        float s = 0.f;
        #pragma unroll
        for (int i = 0; i < 16; i++) { float4 v = p[i]; s += v.x*v.x + v.y*v.y + v.z*v.z + v.w*v.w; }
        mx = fmaxf(mx, s);
    }
    __shared__ float red[256];
    red[tid] = mx; __syncthreads();
    for (int o = 128; o; o >>= 1) { if (tid < o) red[tid] = fmaxf(red[tid], red[tid + o]); __syncthreads(); }
    if (tid == 0) g_kmax[side * 8 + head] = sqrtf(red[0]);
}

// ---------------- f16x3 mma GEMM: C[6144 x 512] = A @ W + bias ---------------
// A: cols<512 from c/d features (concat), cols>=512 from g_att.
// B from transposed weights Wt[j][k]. CTA tile 128x128, warp tile 32x64.
__global__ void __launch_bounds__(256, 2)
gemm_f16(const float* __restrict__ cf, const float* __restrict__ df,
         const float* __restrict__ bias, int wSel, int outSel, int Ktot)
{
    extern __shared__ __half sh[];
    __half* Ahi = sh;                    // [128][PADH]
    __half* Alo = Ahi + 128*PADH;
    __half* Bhi = Alo + 128*PADH;        // [128 n][PADH]
    __half* Blo = Bhi + 128*PADH;
    const float* Wt = (wSel == 0) ? g_WtQ : (wSel == 1) ? g_WtK : (wSel == 2) ? g_WtV : g_WtU;
    float* C = (outSel == 0) ? g_q : (outSel == 1) ? g_k : (outSel == 2) ? g_v : g_h;

    const int tid = threadIdx.x, lane = tid & 31, w = tid >> 5;
    const int wm = w & 3, wn = w >> 2;
    const int rowBase = blockIdx.y * 128, colBase = blockIdx.x * 128;

    float acc[2][8][4];
    #pragma unroll
    for (int mi = 0; mi < 2; mi++)
        #pragma unroll
        for (int nt = 0; nt < 8; nt++)
            #pragma unroll
            for (int j = 0; j < 4; j++) acc[mi][nt][j] = 0.f;

    uint32_t addrA[2];
    #pragma unroll
    for (int mi = 0; mi < 2; mi++)
        addrA[mi] = s2u(Ahi) + (uint32_t)(((wm*32 + mi*16 + (lane & 15)) * PADH + (lane >> 4) * 8) * 2);
    const uint32_t dAlo = (uint32_t)(128 * PADH * 2);

    for (int kc = 0; kc < Ktot / 64; kc++) {
        // A tile 128x64
        #pragma unroll
        for (int i = 0; i < 8; i++) {
            int f = tid + i * 256;
            int r = f >> 4, c = (f & 15) * 4;
            int row = rowBase + r, kk = kc * 64 + c;
            const float* src = (kk < HIDDEN)
                ? ((row < NC) ? cf + (size_t)row * HIDDEN + kk
                              : df + (size_t)(row - NC) * HIDDEN + kk)
                : g_att + (size_t)row * HIDDEN + (kk - HIDDEN);
            float4 v = *(const float4*)src;
            __half h0,h1,h2,h3,l0,l1,l2,l3;
            h_split(v.x,h0,l0); h_split(v.y,h1,l1); h_split(v.z,h2,l2); h_split(v.w,h3,l3);
            __half* ah = Ahi + r * PADH + c;
            __half* al = Alo + r * PADH + c;
            ah[0]=h0; ah[1]=h1; ah[2]=h2; ah[3]=h3;
            al[0]=l0; al[1]=l1; al[2]=l2; al[3]=l3;
        }
        // B tile 128(n)x64(k) from Wt rows
        #pragma unroll
        for (int i = 0; i < 8; i++) {
            int f = tid + i * 256;
            int r = f >> 4, c = (f & 15) * 4;
            float4 v = *(const float4*)(Wt + (size_t)(colBase + r) * Ktot + kc * 64 + c);
            __half h0,h1,h2,h3,l0,l1,l2,l3;
            h_split(v.x,h0,l0); h_split(v.y,h1,l1); h_split(v.z,h2,l2); h_split(v.w,h3,l3);
            __half* bh = Bhi + r * PADH + c;
            __half* bl = Blo + r * PADH + c;
            bh[0]=h0; bh[1]=h1; bh[2]=h2; bh[3]=h3;
            bl[0]=l0; bl[1]=l1; bl[2]=l2; bl[3]=l3;
        }
        __syncthreads();

        #pragma unroll
        for (int ks = 0; ks < 4; ks++) {
            unsigned ahi[2][4], alo[2][4];
            #pragma unroll
            for (int mi = 0; mi < 2; mi++) {
                ldmA(ahi[mi], addrA[mi] + ks * 32);
                ldmA(alo[mi], addrA[mi] + dAlo + ks * 32);
            }
            #pragma unroll
            for (int nt = 0; nt < 8; nt++) {
                const __half* bp = Bhi + (wn*64 + nt*8 + (lane >> 2)) * PADH + ks*16 + (lane & 3)*2;
                const __half* bq = Blo + (wn*64 + nt*8 + (lane >> 2)) * PADH + ks*16 + (lane & 3)*2;
                unsigned bh[2] = { *(const unsigned*)bp, *(const unsigned*)(bp + 8) };
                unsigned bl[2] = { *(const unsigned*)bq, *(const unsigned*)(bq + 8) };
                #pragma unroll
                for (int mi = 0; mi < 2; mi++) {
                    mma_f16(acc[mi][nt], ahi[mi], bh);
                    mma_f16(acc[mi][nt], ahi[mi], bl);
                    mma_f16(acc[mi][nt], alo[mi], bh);
                }
            }
        }
        __syncthreads();
    }
    #pragma unroll
    for (int mi = 0; mi < 2; mi++) {
        int row = rowBase + wm*32 + mi*16 + (lane >> 2);
        #pragma unroll
        for (int nt = 0; nt < 8; nt++) {
            int col = colBase + wn*64 + nt*8 + (lane & 3)*2;
            float b0 = bias[col], b1 = bias[col + 1];
            *(float2*)(C + (size_t)row * HIDDEN + col) =
                make_float2(acc[mi][nt][0] + b0, acc[mi][nt][1] + b1);
            *(float2*)(C + (size_t)(row + 8) * HIDDEN + col) =
                make_float2(acc[mi][nt][2] + b0, acc[mi][nt][3] + b1);
        }
    }
}

// ---------------- f16 mma flash attention ------------------------------------
// grid (48, 8): qt<16 d-side queries, else c-side. 256 thr, warp w: 16 q rows.
__global__ void __launch_bounds__(256, 1)
attn_mma()
{
    extern __shared__ __half smh[];
    __half* Qhi = smh;                   // [128][PADH]
    __half* Qlo = Qhi + 128*PADH;
    __half* Khi = Qlo + 128*PADH;        // [64 key][PADH d]
    __half* Klo = Khi + 64*PADH;
    __half* Vt  = Klo + 64*PADH;         // [64 d][PADH key]
    __half* Pm  = Vt  + 64*PADH;         // [128][PADH]
    unsigned* Mw = (unsigned*)(Pm + 128*PADH);   // [128][2]

    const int tid = threadIdx.x, lane = tid & 31, w = tid >> 5;
    const int qt = blockIdx.x, head = blockIdx.y;
    const bool dside = (qt < 16);
    const int qbase = dside ? NC + qt * 128 : (qt - 16) * 128;
    const int kbase = dside ? 0 : NC;
    const int nkeys = dside ? NC : ND;
    const int qr0 = w * 16;

    // load Q tile, split hi/lo
    #pragma unroll
    for (int i = 0; i < 8; i++) {
        int f = tid + i * 256;
        int r = f >> 4, c = (f & 15) * 4;
        float4 v = *(const float4*)(g_q + (size_t)(qbase + r) * HIDDEN + head * HD + c);
        __half h0,h1,h2,h3,l0,l1,l2,l3;
        h_split(v.x,h0,l0); h_split(v.y,h1,l1); h_split(v.z,h2,l2); h_split(v.w,h3,l3);
        __half* qh = Qhi + r * PADH + c;
        __half* ql = Qlo + r * PADH + c;
        qh[0]=h0; qh[1]=h1; qh[2]=h2; qh[3]=h3;
        ql[0]=l0; ql[1]=l1; ql[2]=l2; ql[3]=l3;
    }
    __syncthreads();

    const int rA = qr0 + (lane >> 2), rB = rA + 8;
    const float kmx = g_kmax[(dside ? 0 : 8) + head];
    const float MqA = g_qn[(qbase + rA) * NHEAD + head] * kmx * 0.125f;
    const float MqB = g_qn[(qbase + rB) * NHEAD + head] * kmx * 0.125f;
    const unsigned* mb = dside ? g_adjT + (size_t)(qbase - NC + tid) * (NC/32)
                               : g_adj  + (size_t)(qbase + tid) * (ND/32);

    const uint32_t aoff = (uint32_t)(((qr0 + (lane & 15)) * PADH + (lane >> 4) * 8) * 2);
    const uint32_t addrQhi = s2u(Qhi) + aoff;
    const uint32_t addrQlo = s2u(Qlo) + aoff;
    const uint32_t addrP   = s2u(Pm)  + aoff;

    float oacc[8][4];
    #pragma unroll
    for (int n = 0; n < 8; n++)
        #pragma unroll
        for (int j = 0; j < 4; j++) oacc[n][j] = 0.f;
    float lA = 0.f, lB = 0.f;

    #pragma unroll 1
    for (int kb = 0; kb < nkeys; kb += 64) {
        // K tile [key][d] split hi/lo (row-major from g_k)
        #pragma unroll
        for (int i = 0; i < 4; i++) {
            int f = tid + i * 256;
            int r = f >> 4, c = (f & 15) * 4;
            float4 v = *(const float4*)(g_k + (size_t)(kbase + kb + r) * HIDDEN + head * HD + c);
            __half h0,h1,h2,h3,l0,l1,l2,l3;
            h_split(v.x,h0,l0); h_split(v.y,h1,l1); h_split(v.z,h2,l2); h_split(v.w,h3,l3);
            __half* kh = Khi + r * PADH + c;
            __half* kl = Klo + r * PADH + c;
            kh[0]=h0; kh[1]=h1; kh[2]=h2; kh[3]=h3;
            kl[0]=l0; kl[1]=l1; kl[2]=l2; kl[3]=l3;
        }
        // V^T tile [d][key], single f16
        #pragma unroll
        for (int i = 0; i < 4; i++) {
            int f = tid + i * 256;
            int d = f >> 4, c = (f & 15) * 4;
            float4 v = *(const float4*)(g_vT + (size_t)(head * HD + d) * NTOT + kbase + kb + c);
            __half* vp = Vt + d * PADH + c;
            vp[0] = __float2half_rn(v.x); vp[1] = __float2half_rn(v.y);
            vp[2] = __float2half_rn(v.z); vp[3] = __float2half_rn(v.w);
        }
        if (tid < 128) {
            Mw[tid * 2]     = mb[(kb >> 5)];
            Mw[tid * 2 + 1] = mb[(kb >> 5) + 1];
        }
        __syncthreads();

        // ---- S = Q K^T (f16 x3) ----
        float sacc[8][4];
        #pragma unroll
        for (int n = 0; n < 8; n++)
            #pragma unroll
            for (int j = 0; j < 4; j++) sacc[n][j] = 0.f;
        #pragma unroll
        for (int ks = 0; ks < 4; ks++) {
            unsigned ahi[4], alo[4];
            ldmA(ahi, addrQhi + ks * 32);
            ldmA(alo, addrQlo + ks * 32);
            #pragma unroll
            for (int nt = 0; nt < 8; nt++) {
                const __half* bp = Khi + (nt*8 + (lane >> 2)) * PADH + ks*16 + (lane & 3)*2;
                const __half* bq = Klo + (nt*8 + (lane >> 2)) * PADH + ks*16 + (lane & 3)*2;
                unsigned bh[2] = { *(const unsigned*)bp, *(const unsigned*)(bp + 8) };
                unsigned bl[2] = { *(const unsigned*)bq, *(const unsigned*)(bq + 8) };
                mma_f16(sacc[nt], ahi, bh);
                mma_f16(sacc[nt], ahi, bl);
                mma_f16(sacc[nt], alo, bh);
            }
        }
        // ---- softmax epilogue (single pass, bound-shifted) ----
        #pragma unroll
        for (int n = 0; n < 8; n++) {
            int colb = n * 8 + 2 * (lane & 3);
            unsigned mwA = Mw[rA * 2 + (colb >> 5)];
            unsigned mwB = Mw[rB * 2 + (colb >> 5)];
            int bit = colb & 31;
            float p0 = ((mwA >> bit) & 1u)       ? __expf(sacc[n][0] * 0.125f - MqA) : 0.f;
            float p1 = ((mwA >> (bit + 1)) & 1u) ? __expf(sacc[n][1] * 0.125f - MqA) : 0.f;
            float p2 = ((mwB >> bit) & 1u)       ? __expf(sacc[n][2] * 0.125f - MqB) : 0.f;
            float p3 = ((mwB >> (bit + 1)) & 1u) ? __expf(sacc[n][3] * 0.125f - MqB) : 0.f;
            lA += p0 + p1; lB += p2 + p3;
            *(__half2*)(Pm + rA * PADH + colb) = __floats2half2_rn(p0, p1);
            *(__half2*)(Pm + rB * PADH + colb) = __floats2half2_rn(p2, p3);
        }
        __syncwarp();
        // ---- O += P V (single f16) ----
        #pragma unroll
        for (int ks = 0; ks < 4; ks++) {
            unsigned ap[4];
            ldmA(ap, addrP + ks * 32);
            #pragma unroll
            for (int nt = 0; nt < 8; nt++) {
                const __half* vp = Vt + (nt*8 + (lane >> 2)) * PADH + ks*16 + (lane & 3)*2;
                unsigned bv[2] = { *(const unsigned*)vp, *(const unsigned*)(vp + 8) };
                mma_f16(oacc[nt], ap, bv);
            }
        }
        __syncthreads();
    }

    lA += __shfl_xor_sync(0xFFFFFFFFu, lA, 1);
    lA += __shfl_xor_sync(0xFFFFFFFFu, lA, 2);
    lB += __shfl_xor_sync(0xFFFFFFFFu, lB, 1);
    lB += __shfl_xor_sync(0xFFFFFFFFu, lB, 2);
    float invA = (lA > 0.f) ? 1.f / lA : 0.f;
    float invB = (lB > 0.f) ? 1.f / lB : 0.f;

    #pragma unroll
    for (int n = 0; n < 8; n++) {
        int colb = head * HD + n * 8 + 2 * (lane & 3);
        *(float2*)(g_att + (size_t)(qbase + rA) * HIDDEN + colb) =
            make_float2(oacc[n][0] * invA, oacc[n][1] * invA);
        *(float2*)(g_att + (size_t)(qbase + rB) * HIDDEN + colb) =
            make_float2(oacc[n][2] * invB, oacc[n][3] * invB);
    }
}

// ---------------- BatchNorm + ReLU -------------------------------------------
__global__ void bn_partial_kernel() {
    int c = threadIdx.x, g = blockIdx.x;
    float s = 0.f, q = 0.f;
    const float* p = g_h + (size_t)g * 128 * HIDDEN + c;
    #pragma unroll 4
    for (int r = 0; r < 128; r++) { float x = p[(size_t)r * HIDDEN]; s += x; q += x * x; }
    g_ps[g * HIDDEN + c] = s;
    g_pq[g * HIDDEN + c] = q;
}
__global__ void bn_final_kernel(const float* __restrict__ gamma, const float* __restrict__ beta) {
    int c = threadIdx.x;
    float s = 0.f, q = 0.f;
    #pragma unroll
    for (int g = 0; g < 48; g++) { s += g_ps[g * HIDDEN + c]; q += g_pq[g * HIDDEN + c]; }
    const float invN = 1.f / (float)NTOT;
    float mu = s * invN, var = q * invN - mu * mu;
    float sc = gamma[c] * rsqrtf(var + 1e-5f);
    g_scale[c] = sc; g_shift[c] = beta[c] - mu * sc;
}
__global__ void bn_apply_kernel(float4* __restrict__ out) {
    int i = blockIdx.x * blockDim.x + threadIdx.x;
    float4 hv = ((const float4*)g_h)[i];
    int c = (i * 4) & (HIDDEN - 1);
    out[i] = make_float4(fmaxf(0.f, hv.x * g_scale[c]   + g_shift[c]),
                         fmaxf(0.f, hv.y * g_scale[c+1] + g_shift[c+1]),
                         fmaxf(0.f, hv.z * g_scale[c+2] + g_shift[c+2]),
                         fmaxf(0.f, hv.w * g_scale[c+3] + g_shift[c+3]));
}

// ---------------- launch ------------------------------------------------------
extern "C" void kernel_launch(void* const* d_in, const int* in_sizes, int n_in,
                              void* d_out, int out_size)
{
    const float* c_feat = (const float*)d_in[0];
    const float* d_feat = (const float*)d_in[1];
    const int*   cd     = (const int*)  d_in[2];
    const float* Wq = (const float*)d_in[3];  const float* bq = (const float*)d_in[4];
    const float* Wk = (const float*)d_in[5];  const float* bk = (const float*)d_in[6];
    const float* Wv = (const float*)d_in[7];  const float* bv = (const float*)d_in[8];
    const float* Wu = (const float*)d_in[9];  const float* bu = (const float*)d_in[10];
    const float* gamma = (const float*)d_in[11];
    const float* beta  = (const float*)d_in[12];
    float* out = (float*)d_out;

    const int GSM = 4 * 128 * PADH * 2;                       // 73728 B
    const int ASM = (128*2 + 64*3 + 128) * PADH * 2 + 128*2*4; // 83968 B
    static int configured = -1;
    if (configured < 0) {
        cudaFuncSetAttribute(gemm_f16, cudaFuncAttributeMaxDynamicSharedMemorySize, GSM);
        cudaFuncSetAttribute(attn_mma, cudaFuncAttributeMaxDynamicSharedMemorySize, ASM);
        configured = 1;
    }

    pack_adj_kernel <<<(NC*(ND/32) + 255)/256, 256>>>(cd);
    pack_adjT_kernel<<<(ND*(NC/32) + 255)/256, 256>>>(cd);

    dim3 tb(32, 8);
    transpose_kernel<<<dim3(16, 16), tb>>>(Wq, 0, 512, 512);
    transpose_kernel<<<dim3(16, 16), tb>>>(Wk, 1, 512, 512);
    transpose_kernel<<<dim3(16, 16), tb>>>(Wv, 2, 512, 512);
    transpose_kernel<<<dim3(16, 32), tb>>>(Wu, 3, 1024, 512);

    dim3 gg(HIDDEN/128, NTOT/128);
    gemm_f16<<<gg, 256, GSM>>>(c_feat, d_feat, bq, 0, 0, 512);
    gemm_f16<<<gg, 256, GSM>>>(c_feat, d_feat, bk, 1, 1, 512);
    gemm_f16<<<gg, 256, GSM>>>(c_feat, d_feat, bv, 2, 2, 512);

    transpose_kernel<<<dim3(16, 192), tb>>>(nullptr, 4, NTOT, 512);
    qn_kernel<<<(NTOT*NHEAD + 255)/256, 256>>>();
    kmax_kernel<<<dim3(NHEAD, 2), 256>>>();

    attn_mma<<<dim3(48, NHEAD), 256, ASM>>>();

    gemm_f16<<<gg, 256, GSM>>>(c_feat, d_feat, bu, 3, 3, 1024);

    bn_partial_kernel<<<48, 512>>>();
    bn_final_kernel<<<1, 512>>>(gamma, beta);
    bn_apply_kernel<<<(NTOT*HIDDEN/4 + 255)/256, 256>>>((float4*)out);
}